// round 2
// baseline (speedup 1.0000x reference)
#include <cuda_runtime.h>
#include <math.h>

// Problem constants
#define BB   256
#define TT   784
#define HH   512
#define NC   10

// Persistent-kernel config: 8 row-blocks x 16 col-blocks = 128 CTAs (<=148 SMs -> co-resident)
#define NBLK 128
#define RBLK 32      // batch rows per CTA
#define CBLK 32      // hidden cols per CTA
#define NTHR 256
#define SMS  34      // smem row stride in floats (even -> float2-aligned, conflict-free)

// Scratch: double-buffered hidden state (1 MB total). Device globals (no alloc).
__device__ __align__(16) float g_h[2][BB * HH];
__device__ unsigned g_cnt = 0;
__device__ volatile unsigned g_gen = 0;

__device__ __forceinline__ void grid_barrier() {
    __syncthreads();
    if (threadIdx.x == 0) {
        unsigned gen = g_gen;            // read generation BEFORE arriving
        __threadfence();                 // release: make my h-writes visible
        if (atomicAdd(&g_cnt, 1u) == NBLK - 1u) {
            g_cnt = 0u;
            __threadfence();
            g_gen = gen + 1u;            // release the pack
        } else {
            while (g_gen == gen) { }     // volatile spin (L2)
        }
        __threadfence();                 // acquire
    }
    __syncthreads();
}

extern "C" __global__ void __launch_bounds__(NTHR, 1)
rnn_persistent(const float* __restrict__ inputs,     // (B, T) f32
               const void* __restrict__ y_raw,       // (B,)   i32 or i64 (detected)
               const void* __restrict__ order_raw,   // (T,)   i32 or i64 (detected)
               const float* __restrict__ W_ih,       // (H,1)  f32
               const float* __restrict__ b_ih,       // (H,)   f32
               const float* __restrict__ W_hh,       // (H,H)  f32
               const float* __restrict__ b_hh,       // (H,)   f32
               const float* __restrict__ lin_W,      // (10,H) f32
               const float* __restrict__ lin_b,      // (10,)  f32
               float* __restrict__ out,              // [loss, correct]
               int out_size)
{
    extern __shared__ float smem[];
    float* h_sm = smem;              // [HH][SMS]  k-major h tile (32 rows)
    float* w_sm = smem + HH * SMS;   // [HH][SMS]  k-major W tile (32 cols), loop-invariant

    // ---- dtype detection: order = arange(784). int32 view index 1 is 1 iff int32,
    // 0 iff int64 little-endian ([0,0, 1,0, 2,0, ...]). Same dtype applies to y.
    const bool is_i64 = (((const int*)order_raw)[1] == 0);

    const int tid   = threadIdx.x;
    const int rb    = blockIdx.x >> 4;   // 0..7
    const int cb    = blockIdx.x & 15;   // 0..15
    const int row0g = rb * RBLK;
    const int col0g = cb * CBLK;

    // ---- Load W_hh slice (32 output cols x 512 K) transposed into smem: ONCE ----
    {
        const int r  = tid >> 3;     // local col index 0..31
        const int c0 = tid & 7;      // float4 chunk phase
        const float4* wsrc = (const float4*)(W_hh + (size_t)(col0g + r) * HH);
        #pragma unroll
        for (int it = 0; it < 16; ++it) {
            int c = c0 + (it << 3);          // 0..127
            float4 v = wsrc[c];
            int k = c << 2;
            w_sm[(k + 0) * SMS + r] = v.x;
            w_sm[(k + 1) * SMS + r] = v.y;
            w_sm[(k + 2) * SMS + r] = v.z;
            w_sm[(k + 3) * SMS + r] = v.w;
        }
    }

    // Thread -> 2x2 output micro-tile
    const int tx  = tid & 15;
    const int ty  = tid >> 4;
    const int r0  = 2 * ty;   // local rows
    const int c0l = 2 * tx;   // local cols

    // Loop-invariant per-thread params
    const float wih0  = W_ih[col0g + c0l];
    const float wih1  = W_ih[col0g + c0l + 1];
    const float bias0 = b_ih[col0g + c0l]     + b_hh[col0g + c0l];
    const float bias1 = b_ih[col0g + c0l + 1] + b_hh[col0g + c0l + 1];

    // Zero h0 (disjoint tiles cover all of g_h[0])
    {
        float2 z = make_float2(0.f, 0.f);
        *(float2*)(g_h[0] + (size_t)(row0g + r0)     * HH + col0g + c0l) = z;
        *(float2*)(g_h[0] + (size_t)(row0g + r0 + 1) * HH + col0g + c0l) = z;
    }
    grid_barrier();

    const int lr  = tid >> 3;   // tile-load row 0..31
    const int lc0 = tid & 7;

    int p = 0;
    for (int t = 0; t < TT; ++t) {
        // ---- load h tile (rows row0g..+31, all K) transposed into smem.
        // __ldcg: MUST bypass L1 (stale lines from 2 steps ago otherwise).
        {
            const float4* hsrc = (const float4*)(g_h[p] + (size_t)(row0g + lr) * HH);
            #pragma unroll
            for (int it = 0; it < 16; ++it) {
                int c = lc0 + (it << 3);
                float4 v = __ldcg(hsrc + c);
                int k = c << 2;
                h_sm[(k + 0) * SMS + lr] = v.x;
                h_sm[(k + 1) * SMS + lr] = v.y;
                h_sm[(k + 2) * SMS + lr] = v.z;
                h_sm[(k + 3) * SMS + lr] = v.w;
            }
        }
        const int ord = is_i64 ? (int)((const long long*)order_raw)[t]
                               : ((const int*)order_raw)[t];
        const float x0 = inputs[(size_t)(row0g + r0)     * TT + ord];
        const float x1 = inputs[(size_t)(row0g + r0 + 1) * TT + ord];
        __syncthreads();

        float a00 = fmaf(x0, wih0, bias0);
        float a01 = fmaf(x0, wih1, bias1);
        float a10 = fmaf(x1, wih0, bias0);
        float a11 = fmaf(x1, wih1, bias1);

        #pragma unroll 8
        for (int k = 0; k < HH; ++k) {
            float2 hv = *(const float2*)&h_sm[k * SMS + r0];
            float2 wv = *(const float2*)&w_sm[k * SMS + c0l];
            a00 = fmaf(hv.x, wv.x, a00);
            a01 = fmaf(hv.x, wv.y, a01);
            a10 = fmaf(hv.y, wv.x, a10);
            a11 = fmaf(hv.y, wv.y, a11);
        }

        float* dst = g_h[p ^ 1];
        float2 o0 = make_float2(tanhf(a00), tanhf(a01));
        float2 o1 = make_float2(tanhf(a10), tanhf(a11));
        *(float2*)(dst + (size_t)(row0g + r0)     * HH + col0g + c0l) = o0;
        *(float2*)(dst + (size_t)(row0g + r0 + 1) * HH + col0g + c0l) = o1;

        grid_barrier();
        p ^= 1;
    }
    // After 784 iterations p == 0; final h lives in g_h[p].

    // ---- Epilogue: classifier head + log-softmax + loss + correct (block 0) ----
    if (blockIdx.x == 0) {
        __shared__ float s_loss[NTHR];
        __shared__ int   s_corr[NTHR];
        const int b = tid;                       // 256 threads == 256 batch rows
        const float* hrow = g_h[p] + (size_t)b * HH;

        float logit[NC];
        #pragma unroll
        for (int c = 0; c < NC; ++c) logit[c] = lin_b[c];

        for (int k = 0; k < HH; k += 4) {
            float4 hv = __ldcg((const float4*)(hrow + k));
            #pragma unroll
            for (int c = 0; c < NC; ++c) {
                float4 wv = *(const float4*)(lin_W + (size_t)c * HH + k);
                logit[c] = fmaf(hv.x, wv.x, logit[c]);
                logit[c] = fmaf(hv.y, wv.y, logit[c]);
                logit[c] = fmaf(hv.z, wv.z, logit[c]);
                logit[c] = fmaf(hv.w, wv.w, logit[c]);
            }
        }

        float m = logit[0]; int pred = 0;
        #pragma unroll
        for (int c = 1; c < NC; ++c)
            if (logit[c] > m) { m = logit[c]; pred = c; }   // first-index ties, like jnp.argmax
        float se = 0.f;
        #pragma unroll
        for (int c = 0; c < NC; ++c) se += expf(logit[c] - m);
        const float lse = m + logf(se);

        const int yb = is_i64 ? (int)((const long long*)y_raw)[b]
                              : ((const int*)y_raw)[b];
        s_loss[tid] = lse - logit[yb];           // -log p_y
        s_corr[tid] = (pred == yb) ? 1 : 0;
        __syncthreads();

        if (tid == 0) {
            float L = 0.f; int C = 0;
            for (int i = 0; i < NTHR; ++i) { L += s_loss[i]; C += s_corr[i]; }
            out[0] = L / (float)BB;
            if (out_size >= 2) out[1] = (float)C;
        }
    }
}

extern "C" void kernel_launch(void* const* d_in, const int* in_sizes, int n_in,
                              void* d_out, int out_size) {
    // Identify inputs by element count (robust to metadata ordering).
    // 200704=inputs, 262144=W_hh, 5120=lin_W, 10=lin_b, 784=order, 256=y,
    // 512 (x3, in encounter order) = W_ih, b_ih, b_hh (biases are zeros, order moot).
    const float *inputs = 0, *W_ih = 0, *b_ih = 0, *W_hh = 0, *b_hh = 0,
                *lin_W = 0, *lin_b = 0;
    const void *y = 0, *order = 0;
    int n512 = 0;
    for (int i = 0; i < n_in; ++i) {
        const int s = in_sizes[i];
        const void* p = d_in[i];
        if      (s == 200704) inputs = (const float*)p;
        else if (s == 262144) W_hh   = (const float*)p;
        else if (s == 5120)   lin_W  = (const float*)p;
        else if (s == 10)     lin_b  = (const float*)p;
        else if (s == 784)    order  = p;
        else if (s == 256)    y      = p;
        else if (s == 512) {
            if      (n512 == 0) W_ih = (const float*)p;
            else if (n512 == 1) b_ih = (const float*)p;
            else                b_hh = (const float*)p;
            ++n512;
        }
    }
    float* out = (float*)d_out;

    const size_t smem_bytes = (size_t)2 * HH * SMS * sizeof(float);  // 139,264 B
    cudaFuncSetAttribute(rnn_persistent,
                         cudaFuncAttributeMaxDynamicSharedMemorySize,
                         (int)smem_bytes);
    rnn_persistent<<<NBLK, NTHR, smem_bytes>>>(inputs, y, order, W_ih, b_ih,
                                               W_hh, b_hh, lin_W, lin_b, out,
                                               out_size);
}

// round 3
// speedup vs baseline: 1.2089x; 1.2089x over previous
#include <cuda_runtime.h>
#include <math.h>

// Problem constants
#define BB   256
#define TT   784
#define HH   512
#define NC   10

// 8 row-groups x 16 col-blocks = 128 CTAs, all co-resident (<=148 SMs, 1 CTA/SM by smem)
#define NBLK 128
#define NTHR 256
#define LDH  524            // smem row stride in floats: 2096 B == 48 mod 128 -> conflict-free

typedef unsigned long long ull;

// Scratch (device globals; no allocation)
__device__ __align__(16) float g_h[2][BB * HH];
__device__ unsigned g_flag[NBLK * 32];   // one flag per CTA, 128B apart; monotonic across replays

__device__ __forceinline__ ull ffma2(ull a, ull b, ull c) {
    ull d;
    asm("fma.rn.f32x2 %0, %1, %2, %3;" : "=l"(d) : "l"(a), "l"(b), "l"(c));
    return d;
}
__device__ __forceinline__ float2 u2f(ull v) {
    float2 f;
    asm("mov.b64 {%0, %1}, %2;" : "=f"(f.x), "=f"(f.y) : "l"(v));
    return f;
}
__device__ __forceinline__ void st_release(unsigned* p, unsigned v) {
    asm volatile("st.release.gpu.global.u32 [%0], %1;" :: "l"(p), "r"(v) : "memory");
}
__device__ __forceinline__ unsigned ld_acquire(const unsigned* p) {
    unsigned v;
    asm volatile("ld.acquire.gpu.global.u32 %0, [%1];" : "=r"(v) : "l"(p) : "memory");
    return v;
}

extern "C" __global__ void __launch_bounds__(NTHR, 1)
rnn_persistent(const float* __restrict__ inputs,     // (B, T) f32
               const void* __restrict__ y_raw,       // (B,)   i32/i64 (detected)
               const void* __restrict__ order_raw,   // (T,)   i32/i64 (detected)
               const float* __restrict__ W_ih,       // (H,1)
               const float* __restrict__ b_ih,       // (H,)
               const float* __restrict__ W_hh,       // (H,H)
               const float* __restrict__ b_hh,       // (H,)
               const float* __restrict__ lin_W,      // (10,H)
               const float* __restrict__ lin_b,      // (10,)
               float* __restrict__ out, int out_size)
{
    extern __shared__ float smem[];
    float* h_sm   = smem;                      // [32][LDH]
    float* w_sm   = smem + 32 * LDH;           // [32][LDH]
    int*   s_ord  = (int*)(smem + 64 * LDH);   // [TT]
    unsigned* s_u = (unsigned*)(s_ord + TT);   // [0]=base

    const int tid = threadIdx.x;
    const int rb  = blockIdx.x >> 4;           // row group 0..7
    const int cb  = blockIdx.x & 15;           // col block 0..15
    const int row0g = rb * 32;
    const int col0g = cb * 32;

    const bool is_i64 = (((const int*)order_raw)[1] == 0);   // arange detect

    // base = my own flag at entry (uniform: every launch adds exactly 785 to every flag)
    if (tid == 0) s_u[0] = g_flag[blockIdx.x * 32];
    // order -> smem (converted to int)
    for (int i = tid; i < TT; i += NTHR)
        s_ord[i] = is_i64 ? (int)((const long long*)order_raw)[i] : ((const int*)order_raw)[i];

    // ---- W_hh slice into smem, row-major [c_local][k]: ONCE ----
    {
        const int r  = tid >> 3;       // local col 0..31
        const int ph = tid & 7;
        const float4* src = (const float4*)(W_hh + (size_t)(col0g + r) * HH);
        float* dst = w_sm + r * LDH;
        #pragma unroll
        for (int it = 0; it < 16; ++it) {
            int c = ph + (it << 3);
            *(float4*)(dst + 4 * c) = src[c];
        }
    }

    // Thread -> outputs: warp = 8 rows x 16 cols; thread: rows {ly, ly+4}, cols {lx, lx+8}
    const int warp = tid >> 5, lane = tid & 31;
    const int wr = warp & 3, wc = warp >> 2;
    const int ly = lane >> 3, lx = lane & 7;
    const int lr0 = wr * 8 + ly;                  // local rows lr0, lr0+4
    const int lc0 = wc * 16 + lx;                 // local cols lc0, lc0+8
    const int grow0 = row0g + lr0, grow1 = grow0 + 4;
    const int gcol0 = col0g + lc0, gcol1 = gcol0 + 8;

    const float wih0  = W_ih[gcol0], wih1 = W_ih[gcol1];
    const float bias0 = b_ih[gcol0] + b_hh[gcol0];
    const float bias1 = b_ih[gcol1] + b_hh[gcol1];

    // Zero h0 for our tile (union over all CTAs covers g_h[0])
    {
        int zr = tid >> 3, zc = (tid & 7) << 2;
        *(float4*)(g_h[0] + (size_t)(row0g + zr) * HH + col0g + zc) =
            make_float4(0.f, 0.f, 0.f, 0.f);
    }
    __syncthreads();
    const unsigned base = s_u[0];
    if (tid == 0) st_release(&g_flag[blockIdx.x * 32], base + 1);   // h0 ready

    const int fr = tid >> 3, fp = tid & 7;        // per-step h-tile fill mapping
    const float* ph0 = h_sm + lr0 * LDH;
    const float* pw0 = w_sm + lc0 * LDH;

    int p = 0;
    for (int t = 0; t < TT; ++t) {
        const int ord = s_ord[t];
        const float x0 = inputs[(size_t)grow0 * TT + ord];   // issued early, used late
        const float x1 = inputs[(size_t)grow1 * TT + ord];

        // ---- wait for my row group (16 CTAs) to have published buffer p ----
        if (tid < 16) {
            const unsigned* fl = &g_flag[((rb << 4) + tid) * 32];
            unsigned v;
            do { v = ld_acquire(fl); } while ((int)(v - (base + 1 + (unsigned)t)) < 0);
        }
        __syncthreads();

        // ---- fill h tile [32][512] row-major (L1 bypass: lines are stale) ----
        {
            const float4* src = (const float4*)(g_h[p] + (size_t)(row0g + fr) * HH);
            float* dst = h_sm + fr * LDH;
            #pragma unroll
            for (int it = 0; it < 16; ++it) {
                int c = fp + (it << 3);
                *(float4*)(dst + 4 * c) = __ldcg(src + c);
            }
        }
        __syncthreads();

        // ---- 2x2 outputs, k packed in f32x2 pairs; 8 independent accumulator chains ----
        ull A00a = 0, A00b = 0, A01a = 0, A01b = 0;
        ull A10a = 0, A10b = 0, A11a = 0, A11b = 0;
        #pragma unroll 8
        for (int k = 0; k < HH; k += 4) {
            ulonglong2 H0 = *(const ulonglong2*)(ph0 + k);
            ulonglong2 H1 = *(const ulonglong2*)(ph0 + 4 * LDH + k);
            ulonglong2 W0 = *(const ulonglong2*)(pw0 + k);
            ulonglong2 W1 = *(const ulonglong2*)(pw0 + 8 * LDH + k);
            A00a = ffma2(H0.x, W0.x, A00a);  A00b = ffma2(H0.y, W0.y, A00b);
            A01a = ffma2(H0.x, W1.x, A01a);  A01b = ffma2(H0.y, W1.y, A01b);
            A10a = ffma2(H1.x, W0.x, A10a);  A10b = ffma2(H1.y, W0.y, A10b);
            A11a = ffma2(H1.x, W1.x, A11a);  A11b = ffma2(H1.y, W1.y, A11b);
        }
        float2 f;
        float a00, a01, a10, a11;
        f = u2f(A00a); a00  = f.x + f.y;  f = u2f(A00b); a00 += f.x + f.y;
        f = u2f(A01a); a01  = f.x + f.y;  f = u2f(A01b); a01 += f.x + f.y;
        f = u2f(A10a); a10  = f.x + f.y;  f = u2f(A10b); a10 += f.x + f.y;
        f = u2f(A11a); a11  = f.x + f.y;  f = u2f(A11b); a11 += f.x + f.y;
        a00 = tanhf(fmaf(x0, wih0, bias0) + a00);
        a01 = tanhf(fmaf(x0, wih1, bias1) + a01);
        a10 = tanhf(fmaf(x1, wih0, bias0) + a10);
        a11 = tanhf(fmaf(x1, wih1, bias1) + a11);

        float* dst = g_h[p ^ 1];
        dst[(size_t)grow0 * HH + gcol0] = a00;
        dst[(size_t)grow0 * HH + gcol1] = a01;
        dst[(size_t)grow1 * HH + gcol0] = a10;
        dst[(size_t)grow1 * HH + gcol1] = a11;

        __syncthreads();   // all tile stores done (bar orders them before the release)
        if (tid == 0) st_release(&g_flag[blockIdx.x * 32], base + 2 + (unsigned)t);
        p ^= 1;
    }
    // final h in g_h[0] (784 steps, even)

    // ---- Epilogue on block 0: wait whole grid, then head + log-softmax ----
    if (blockIdx.x == 0) {
        if (tid < NBLK) {
            const unsigned* fl = &g_flag[tid * 32];
            unsigned v;
            do { v = ld_acquire(fl); } while ((int)(v - (base + 1 + TT)) < 0);
        }
        __syncthreads();

        __shared__ float s_loss[NTHR];
        __shared__ int   s_corr[NTHR];
        const int b = tid;
        const float* hrow = g_h[0] + (size_t)b * HH;

        float logit[NC];
        #pragma unroll
        for (int c = 0; c < NC; ++c) logit[c] = lin_b[c];
        for (int k = 0; k < HH; k += 4) {
            float4 hv = __ldcg((const float4*)(hrow + k));
            #pragma unroll
            for (int c = 0; c < NC; ++c) {
                float4 wv = *(const float4*)(lin_W + (size_t)c * HH + k);
                logit[c] = fmaf(hv.x, wv.x, logit[c]);
                logit[c] = fmaf(hv.y, wv.y, logit[c]);
                logit[c] = fmaf(hv.z, wv.z, logit[c]);
                logit[c] = fmaf(hv.w, wv.w, logit[c]);
            }
        }
        float m = logit[0]; int pred = 0;
        #pragma unroll
        for (int c = 1; c < NC; ++c)
            if (logit[c] > m) { m = logit[c]; pred = c; }
        float se = 0.f;
        #pragma unroll
        for (int c = 0; c < NC; ++c) se += expf(logit[c] - m);
        const float lse = m + logf(se);

        const int yb = is_i64 ? (int)((const long long*)y_raw)[b]
                              : ((const int*)y_raw)[b];
        s_loss[tid] = lse - logit[yb];
        s_corr[tid] = (pred == yb) ? 1 : 0;
        __syncthreads();
        if (tid == 0) {
            float L = 0.f; int C = 0;
            for (int i = 0; i < NTHR; ++i) { L += s_loss[i]; C += s_corr[i]; }
            out[0] = L / (float)BB;
            if (out_size >= 2) out[1] = (float)C;
        }
    }
}

extern "C" void kernel_launch(void* const* d_in, const int* in_sizes, int n_in,
                              void* d_out, int out_size) {
    // Identify inputs by element count (robust to ordering).
    const float *inputs = 0, *W_ih = 0, *b_ih = 0, *W_hh = 0, *b_hh = 0,
                *lin_W = 0, *lin_b = 0;
    const void *y = 0, *order = 0;
    int n512 = 0;
    for (int i = 0; i < n_in; ++i) {
        const int s = in_sizes[i];
        const void* ptr = d_in[i];
        if      (s == 200704) inputs = (const float*)ptr;
        else if (s == 262144) W_hh   = (const float*)ptr;
        else if (s == 5120)   lin_W  = (const float*)ptr;
        else if (s == 10)     lin_b  = (const float*)ptr;
        else if (s == 784)    order  = ptr;
        else if (s == 256)    y      = ptr;
        else if (s == 512) {
            if      (n512 == 0) W_ih = (const float*)ptr;
            else if (n512 == 1) b_ih = (const float*)ptr;
            else                b_hh = (const float*)ptr;
            ++n512;
        }
    }
    float* out = (float*)d_out;

    // smem: h[32][524] + w[32][524] + order[784] + 1 word, rounded up
    const size_t smem_bytes = (size_t)64 * LDH * sizeof(float) + TT * sizeof(int) + 64;
    cudaFuncSetAttribute(rnn_persistent,
                         cudaFuncAttributeMaxDynamicSharedMemorySize, (int)smem_bytes);
    rnn_persistent<<<NBLK, NTHR, smem_bytes>>>(inputs, y, order, W_ih, b_ih,
                                               W_hh, b_hh, lin_W, lin_b, out,
                                               out_size);
}

// round 4
// speedup vs baseline: 1.6404x; 1.3569x over previous
#include <cuda_runtime.h>
#include <math.h>

// Problem constants
#define BB   256
#define TT   784
#define HH   512
#define NC   10

// 8 row-groups x 16 col-blocks = 128 CTAs, all co-resident (1 CTA/SM)
#define NBLK 128
#define NTHR 256
#define LDH  516            // smem row stride in floats: mod 32 == 4 -> W loads conflict-free

typedef unsigned long long ull;

// Scratch (device globals; no allocation)
__device__ __align__(16) float g_h[2][BB * HH];
__device__ unsigned g_flag[NBLK * 32];   // one flag per CTA, 128B apart; monotonic across replays

__device__ __forceinline__ ull ffma2(ull a, ull b, ull c) {
    ull d;
    asm("fma.rn.f32x2 %0, %1, %2, %3;" : "=l"(d) : "l"(a), "l"(b), "l"(c));
    return d;
}
__device__ __forceinline__ float u2sum(ull v) {
    float lo, hi;
    asm("mov.b64 {%0, %1}, %2;" : "=f"(lo), "=f"(hi) : "l"(v));
    return lo + hi;
}
__device__ __forceinline__ void st_release(unsigned* p, unsigned v) {
    asm volatile("st.release.gpu.global.u32 [%0], %1;" :: "l"(p), "r"(v) : "memory");
}
__device__ __forceinline__ unsigned ld_acquire(const unsigned* p) {
    unsigned v;
    asm volatile("ld.acquire.gpu.global.u32 %0, [%1];" : "=r"(v) : "l"(p) : "memory");
    return v;
}
__device__ __forceinline__ void bar_named(int id, int cnt) {
    asm volatile("bar.sync %0, %1;" :: "r"(id), "r"(cnt) : "memory");
}

extern "C" __global__ void __launch_bounds__(NTHR, 1)
rnn_persistent(const float* __restrict__ inputs,     // (B, T) f32
               const void* __restrict__ y_raw,       // (B,)   i32/i64 (detected)
               const void* __restrict__ order_raw,   // (T,)   i32/i64 (detected)
               const float* __restrict__ W_ih,       // (H,1)
               const float* __restrict__ b_ih,       // (H,)
               const float* __restrict__ W_hh,       // (H,H)
               const float* __restrict__ b_hh,       // (H,)
               const float* __restrict__ lin_W,      // (10,H)
               const float* __restrict__ lin_b,      // (10,)
               float* __restrict__ out, int out_size)
{
    extern __shared__ float smem[];
    float* w_sm    = smem;                     // [32][LDH]
    float* h_sm    = smem + 32 * LDH;          // [32][LDH]  (aliased as reduce scratch)
    float* scratch = h_sm;                     // [3][64][20] = 3840 floats, fits easily
    int*   s_ord   = (int*)(smem + 64 * LDH);  // [TT]
    unsigned* s_u  = (unsigned*)(s_ord + TT);  // [0]=base

    const int tid = threadIdx.x;
    const int g   = tid >> 6;            // k-group 0..3, owns k in [128g, 128g+128)
    const int t64 = tid & 63;            // thread in group
    const int ty  = t64 >> 3;            // 0..7  -> rows {ty, ty+8, ty+16, ty+24}
    const int tx  = t64 & 7;             // 0..7  -> cols {tx, tx+8, tx+16, tx+24}

    const int rb    = blockIdx.x >> 4;   // row group 0..7
    const int cb    = blockIdx.x & 15;   // col block 0..15
    const int row0g = rb * 32;
    const int col0g = cb * 32;

    const bool is_i64 = (((const int*)order_raw)[1] == 0);   // arange detect

    if (tid == 0) s_u[0] = g_flag[blockIdx.x * 32];
    for (int i = tid; i < TT; i += NTHR)
        s_ord[i] = is_i64 ? (int)((const long long*)order_raw)[i] : ((const int*)order_raw)[i];

    // ---- W_hh slice into smem, [c_local][k] stride LDH: ONCE ----
    {
        const int c  = tid >> 3;         // local col 0..31
        const int p0 = tid & 7;
        const float4* src = (const float4*)(W_hh + (size_t)(col0g + c) * HH);
        float* dst = w_sm + c * LDH;
        #pragma unroll
        for (int it = 0; it < 16; ++it) {
            int cc = p0 + (it << 3);
            *(float4*)(dst + 4 * cc) = src[cc];
        }
    }

    // Per-thread loop-invariant col params (cols tx+8j)
    float wihv[4], biasv[4];
    #pragma unroll
    for (int j = 0; j < 4; ++j) {
        int c = col0g + tx + 8 * j;
        wihv[j]  = W_ih[c];
        biasv[j] = b_ih[c] + b_hh[c];
    }

    // Zero h0 for our tile
    {
        int zr = tid >> 3, zc = (tid & 7) << 2;
        *(float4*)(g_h[0] + (size_t)(row0g + zr) * HH + col0g + zc) =
            make_float4(0.f, 0.f, 0.f, 0.f);
    }
    __syncthreads();
    const unsigned base = s_u[0];
    if (tid == 0) st_release(&g_flag[blockIdx.x * 32], base + 1);   // h0 ready

    // Precomputed pointers
    const float* hb[4];
    const float* wb[4];
    #pragma unroll
    for (int i = 0; i < 4; ++i) hb[i] = h_sm + (ty + 8 * i) * LDH + 128 * g;
    #pragma unroll
    for (int j = 0; j < 4; ++j) wb[j] = w_sm + (tx + 8 * j) * LDH + 128 * g;

    // Fill mapping: rows r=(t64>>3)+8j, chunks cc=(t64&7)+8i  (LDG coalesced, STS conflict-free)
    const int fr0 = t64 >> 3, fc0 = t64 & 7;

    int p = 0;
    for (int t = 0; t < TT; ++t) {
        // ---- A: wait for my row group (16 CTAs) to have published buffer p ----
        if (tid < 16) {
            const unsigned* fl = &g_flag[((rb << 4) + tid) * 32];
            unsigned v;
            do { v = ld_acquire(fl); } while ((int)(v - (base + 1 + (unsigned)t)) < 0);
        }
        __syncthreads();

        const int ord = s_ord[t];
        float xv[4];
        if (g == 0) {                    // prefetch x for epilogue rows
            #pragma unroll
            for (int i = 0; i < 4; ++i)
                xv[i] = inputs[(size_t)(row0g + ty + 8 * i) * TT + ord];
        }

        // ---- fill my k-slice of the h tile (L1 bypass: lines are stale) ----
        {
            #pragma unroll
            for (int j = 0; j < 4; ++j) {
                const int r = fr0 + 8 * j;
                const float4* src = (const float4*)(g_h[p] + (size_t)(row0g + r) * HH + 128 * g);
                float* dst = h_sm + r * LDH + 128 * g;
                #pragma unroll
                for (int i = 0; i < 4; ++i) {
                    int cc = fc0 + 8 * i;
                    *(float4*)(dst + 4 * cc) = __ldcg(src + cc);
                }
            }
        }
        bar_named(1 + g, 64);            // my group's slice visible to both its warps

        // ---- 4x4 microtile over my 128-k range; f32x2-packed accumulators ----
        ull a00 = 0, a01 = 0, a02 = 0, a03 = 0;
        ull a10 = 0, a11 = 0, a12 = 0, a13 = 0;
        ull a20 = 0, a21 = 0, a22 = 0, a23 = 0;
        ull a30 = 0, a31 = 0, a32 = 0, a33 = 0;
        #pragma unroll 2
        for (int kk = 0; kk < 128; kk += 4) {
            ulonglong2 H0 = *(const ulonglong2*)(hb[0] + kk);
            ulonglong2 H1 = *(const ulonglong2*)(hb[1] + kk);
            ulonglong2 H2 = *(const ulonglong2*)(hb[2] + kk);
            ulonglong2 H3 = *(const ulonglong2*)(hb[3] + kk);
            ulonglong2 W0 = *(const ulonglong2*)(wb[0] + kk);
            ulonglong2 W1 = *(const ulonglong2*)(wb[1] + kk);
            ulonglong2 W2 = *(const ulonglong2*)(wb[2] + kk);
            ulonglong2 W3 = *(const ulonglong2*)(wb[3] + kk);
            a00 = ffma2(H0.x, W0.x, a00); a00 = ffma2(H0.y, W0.y, a00);
            a01 = ffma2(H0.x, W1.x, a01); a01 = ffma2(H0.y, W1.y, a01);
            a02 = ffma2(H0.x, W2.x, a02); a02 = ffma2(H0.y, W2.y, a02);
            a03 = ffma2(H0.x, W3.x, a03); a03 = ffma2(H0.y, W3.y, a03);
            a10 = ffma2(H1.x, W0.x, a10); a10 = ffma2(H1.y, W0.y, a10);
            a11 = ffma2(H1.x, W1.x, a11); a11 = ffma2(H1.y, W1.y, a11);
            a12 = ffma2(H1.x, W2.x, a12); a12 = ffma2(H1.y, W2.y, a12);
            a13 = ffma2(H1.x, W3.x, a13); a13 = ffma2(H1.y, W3.y, a13);
            a20 = ffma2(H2.x, W0.x, a20); a20 = ffma2(H2.y, W0.y, a20);
            a21 = ffma2(H2.x, W1.x, a21); a21 = ffma2(H2.y, W1.y, a21);
            a22 = ffma2(H2.x, W2.x, a22); a22 = ffma2(H2.y, W2.y, a22);
            a23 = ffma2(H2.x, W3.x, a23); a23 = ffma2(H2.y, W3.y, a23);
            a30 = ffma2(H3.x, W0.x, a30); a30 = ffma2(H3.y, W0.y, a30);
            a31 = ffma2(H3.x, W1.x, a31); a31 = ffma2(H3.y, W1.y, a31);
            a32 = ffma2(H3.x, W2.x, a32); a32 = ffma2(H3.y, W2.y, a32);
            a33 = ffma2(H3.x, W3.x, a33); a33 = ffma2(H3.y, W3.y, a33);
        }
        float s[4][4];
        s[0][0] = u2sum(a00); s[0][1] = u2sum(a01); s[0][2] = u2sum(a02); s[0][3] = u2sum(a03);
        s[1][0] = u2sum(a10); s[1][1] = u2sum(a11); s[1][2] = u2sum(a12); s[1][3] = u2sum(a13);
        s[2][0] = u2sum(a20); s[2][1] = u2sum(a21); s[2][2] = u2sum(a22); s[2][3] = u2sum(a23);
        s[3][0] = u2sum(a30); s[3][1] = u2sum(a31); s[3][2] = u2sum(a32); s[3][3] = u2sum(a33);

        __syncthreads();   // B: all groups done reading h_sm (scratch aliases it)

        if (g > 0) {       // publish partials: [g-1][t64][20] stride-20 -> conflict-free STS.128
            float* dst = scratch + (size_t)(g - 1) * 1280 + t64 * 20;
            #pragma unroll
            for (int i = 0; i < 4; ++i)
                *(float4*)(dst + 4 * i) = make_float4(s[i][0], s[i][1], s[i][2], s[i][3]);
        }
        __syncthreads();   // C: partials visible

        if (g == 0) {
            #pragma unroll
            for (int gg = 0; gg < 3; ++gg) {
                const float* src = scratch + (size_t)gg * 1280 + t64 * 20;
                #pragma unroll
                for (int i = 0; i < 4; ++i) {
                    float4 v = *(const float4*)(src + 4 * i);
                    s[i][0] += v.x; s[i][1] += v.y; s[i][2] += v.z; s[i][3] += v.w;
                }
            }
            float* dst = g_h[p ^ 1];
            #pragma unroll
            for (int i = 0; i < 4; ++i) {
                const size_t rowoff = (size_t)(row0g + ty + 8 * i) * HH + col0g;
                #pragma unroll
                for (int j = 0; j < 4; ++j) {
                    float v = tanhf(fmaf(xv[i], wihv[j], biasv[j]) + s[i][j]);
                    dst[rowoff + tx + 8 * j] = v;
                }
            }
            bar_named(1, 64);            // group 0's stores done
            if (t64 == 0) st_release(&g_flag[blockIdx.x * 32], base + 2 + (unsigned)t);
        }
        p ^= 1;
    }
    // final h in g_h[0] (784 steps, even)

    // ---- Epilogue on block 0: wait whole grid, then head + log-softmax ----
    if (blockIdx.x == 0) {
        if (tid < NBLK) {
            const unsigned* fl = &g_flag[tid * 32];
            unsigned v;
            do { v = ld_acquire(fl); } while ((int)(v - (base + 1 + TT)) < 0);
        }
        __syncthreads();

        __shared__ float s_loss[NTHR];
        __shared__ int   s_corr[NTHR];
        const int b = tid;
        const float* hrow = g_h[0] + (size_t)b * HH;

        float logit[NC];
        #pragma unroll
        for (int c = 0; c < NC; ++c) logit[c] = lin_b[c];
        for (int k = 0; k < HH; k += 4) {
            float4 hv = __ldcg((const float4*)(hrow + k));
            #pragma unroll
            for (int c = 0; c < NC; ++c) {
                float4 wv = *(const float4*)(lin_W + (size_t)c * HH + k);
                logit[c] = fmaf(hv.x, wv.x, logit[c]);
                logit[c] = fmaf(hv.y, wv.y, logit[c]);
                logit[c] = fmaf(hv.z, wv.z, logit[c]);
                logit[c] = fmaf(hv.w, wv.w, logit[c]);
            }
        }
        float m = logit[0]; int pred = 0;
        #pragma unroll
        for (int c = 1; c < NC; ++c)
            if (logit[c] > m) { m = logit[c]; pred = c; }
        float se = 0.f;
        #pragma unroll
        for (int c = 0; c < NC; ++c) se += expf(logit[c] - m);
        const float lse = m + logf(se);

        const int yb = is_i64 ? (int)((const long long*)y_raw)[b]
                              : ((const int*)y_raw)[b];
        s_loss[tid] = lse - logit[yb];
        s_corr[tid] = (pred == yb) ? 1 : 0;
        __syncthreads();
        if (tid == 0) {
            float L = 0.f; int C = 0;
            for (int i = 0; i < NTHR; ++i) { L += s_loss[i]; C += s_corr[i]; }
            out[0] = L / (float)BB;
            if (out_size >= 2) out[1] = (float)C;
        }
    }
}

extern "C" void kernel_launch(void* const* d_in, const int* in_sizes, int n_in,
                              void* d_out, int out_size) {
    // Identify inputs by element count (robust to ordering).
    const float *inputs = 0, *W_ih = 0, *b_ih = 0, *W_hh = 0, *b_hh = 0,
                *lin_W = 0, *lin_b = 0;
    const void *y = 0, *order = 0;
    int n512 = 0;
    for (int i = 0; i < n_in; ++i) {
        const int s = in_sizes[i];
        const void* ptr = d_in[i];
        if      (s == 200704) inputs = (const float*)ptr;
        else if (s == 262144) W_hh   = (const float*)ptr;
        else if (s == 5120)   lin_W  = (const float*)ptr;
        else if (s == 10)     lin_b  = (const float*)ptr;
        else if (s == 784)    order  = ptr;
        else if (s == 256)    y      = ptr;
        else if (s == 512) {
            if      (n512 == 0) W_ih = (const float*)ptr;
            else if (n512 == 1) b_ih = (const float*)ptr;
            else                b_hh = (const float*)ptr;
            ++n512;
        }
    }
    float* out = (float*)d_out;

    // smem: w[32][516] + h[32][516] + order[784] + 1 word
    const size_t smem_bytes = (size_t)64 * LDH * sizeof(float) + TT * sizeof(int) + 64;
    cudaFuncSetAttribute(rnn_persistent,
                         cudaFuncAttributeMaxDynamicSharedMemorySize, (int)smem_bytes);
    rnn_persistent<<<NBLK, NTHR, smem_bytes>>>(inputs, y, order, W_ih, b_ih,
                                               W_hh, b_hh, lin_W, lin_b, out,
                                               out_size);
}

// round 7
// speedup vs baseline: 1.7372x; 1.0591x over previous
#include <cuda_runtime.h>
#include <math.h>

// Problem constants
#define BB   256
#define TT   784
#define HH   512
#define NC   10

// 8 row-groups x 16 col-blocks = 128 CTAs, all co-resident (1 CTA/SM)
#define NBLK 128
#define NTHR 512
#define NG   8              // k-groups per CTA
#define KR   64             // k-range per group (NG*KR = HH)
#define LDH  516            // smem row stride in floats: mod 32 == 4 -> conflict-free patterns
#define SCR  20             // scratch stride (floats) per (group,thread)
#define SPIN_CAP 10000000u  // watchdog: real waits are <1e3 polls; cap turns hang into signal

typedef unsigned long long ull;

// Scratch (device globals; no allocation)
__device__ __align__(16) float g_h[2][BB * HH];
__device__ unsigned g_flag[NBLK * 32];   // one flag per CTA, 128B apart; monotonic across replays

__device__ __forceinline__ ull ffma2(ull a, ull b, ull c) {
    ull d;
    asm("fma.rn.f32x2 %0, %1, %2, %3;" : "=l"(d) : "l"(a), "l"(b), "l"(c));
    return d;
}
__device__ __forceinline__ float u2sum(ull v) {
    float lo, hi;
    asm("mov.b64 {%0, %1}, %2;" : "=f"(lo), "=f"(hi) : "l"(v));
    return lo + hi;
}
__device__ __forceinline__ void st_release(unsigned* p, unsigned v) {
    asm volatile("st.release.gpu.global.u32 [%0], %1;" :: "l"(p), "r"(v) : "memory");
}
__device__ __forceinline__ unsigned ld_acquire(const unsigned* p) {
    unsigned v;
    asm volatile("ld.acquire.gpu.global.u32 %0, [%1];" : "=r"(v) : "l"(p) : "memory");
    return v;
}
__device__ __forceinline__ void bar_named(int id, int cnt) {
    asm volatile("bar.sync %0, %1;" :: "r"(id), "r"(cnt) : "memory");
}
// Bounded acquire-spin: waits until *p - target >= 0 (wrap-safe) or watchdog cap.
__device__ __forceinline__ void spin_until(const unsigned* p, unsigned target) {
    unsigned v, n = 0;
    do { v = ld_acquire(p); } while ((int)(v - target) < 0 && ++n < SPIN_CAP);
}

extern "C" __global__ void __launch_bounds__(NTHR, 1)
rnn_persistent(const float* __restrict__ inputs,     // (B, T) f32
               const void* __restrict__ y_raw,       // (B,)   i32/i64 (detected)
               const void* __restrict__ order_raw,   // (T,)   i32/i64 (detected)
               const float* __restrict__ W_ih,       // (H,1)
               const float* __restrict__ b_ih,       // (H,)
               const float* __restrict__ W_hh,       // (H,H)
               const float* __restrict__ b_hh,       // (H,)
               const float* __restrict__ lin_W,      // (10,H)
               const float* __restrict__ lin_b,      // (10,)
               float* __restrict__ out, int out_size)
{
    extern __shared__ float smem[];
    float* w_sm    = smem;                         // [32][LDH]
    float* h_sm    = smem + 32 * LDH;              // [32][LDH]
    float* scratch = smem + 64 * LDH;              // [NG][64][SCR]
    int*   s_ord   = (int*)(scratch + NG * 64 * SCR);  // [TT]
    float* s_x     = (float*)(s_ord + TT);         // [32] x_t per local row
    float* s_wb    = s_x + 32;                     // [0..31]=w_ih, [32..63]=bias per local col
    unsigned* s_u  = (unsigned*)(s_wb + 64);       // [0]=base

    const int tid = threadIdx.x;
    const int g   = tid >> 6;            // k-group 0..7, owns k in [KR*g, KR*g+KR)
    const int t64 = tid & 63;
    const int ty  = t64 >> 3;            // 0..7  -> rows {ty, ty+8, ty+16, ty+24}
    const int tx  = t64 & 7;             // 0..7  -> cols {tx, tx+8, tx+16, tx+24}

    const int rb    = blockIdx.x >> 4;   // row group 0..7
    const int cb    = blockIdx.x & 15;   // col block 0..15
    const int row0g = rb * 32;
    const int col0g = cb * 32;

    const bool is_i64 = (((const int*)order_raw)[1] == 0);   // arange detect

    if (tid == 0) s_u[0] = g_flag[blockIdx.x * 32];
    for (int i = tid; i < TT; i += NTHR)
        s_ord[i] = is_i64 ? (int)((const long long*)order_raw)[i] : ((const int*)order_raw)[i];

    // ---- W_hh slice into smem, [c_local][k] stride LDH: ONCE ----
    {
        const int c  = tid >> 4;         // local col 0..31
        const int p0 = tid & 15;
        const float4* src = (const float4*)(W_hh + (size_t)(col0g + c) * HH);
        float* dst = w_sm + c * LDH;
        #pragma unroll
        for (int it = 0; it < 8; ++it) {
            int cc = p0 + (it << 4);
            *(float4*)(dst + 4 * cc) = src[cc];
        }
    }
    // Per-col params into smem
    if (tid < 32) {
        int c = col0g + tid;
        s_wb[tid]      = W_ih[c];
        s_wb[32 + tid] = b_ih[c] + b_hh[c];
    }
    // Zero h0 for our tile
    {
        int zr = tid >> 4, zc = (tid & 15) << 1;
        *(float2*)(g_h[0] + (size_t)(row0g + zr) * HH + col0g + zc) = make_float2(0.f, 0.f);
    }
    __syncthreads();
    const unsigned base = s_u[0];
    if (tid == 0) st_release(&g_flag[blockIdx.x * 32], base + 1);   // h0 ready

    // Compute-phase pointers
    const float* hb[4];
    const float* wb[4];
    #pragma unroll
    for (int i = 0; i < 4; ++i) hb[i] = h_sm + (ty + 8 * i) * LDH + KR * g;
    #pragma unroll
    for (int j = 0; j < 4; ++j) wb[j] = w_sm + (tx + 8 * j) * LDH + KR * g;

    // Fill mapping: rows fr0+4j (j=0..7), float4 chunk fcc within my 64-float slice
    const int fr0 = t64 >> 4, fcc = t64 & 15;

    // Reduce mapping: thread reduces outputs o = 2*tid, 2*tid+1 (same row, cols +8 apart)
    const int t64o  = (2 * tid) >> 4;          // owner thread in group coords
    const int idx   = (2 * tid) & 15;          // even
    const int ri    = idx >> 2;
    const int row_l = (t64o >> 3) + 8 * ri;
    const int col0l = (t64o & 7) + 8 * (idx & 3);
    const int col1l = col0l + 8;

    int p = 0;
    for (int t = 0; t < TT; ++t) {
        const int ord = s_ord[t];
        // x prefetch (independent of h) by last warp
        if (tid >= NTHR - 32) {
            int r = tid - (NTHR - 32);
            s_x[r] = inputs[(size_t)(row0g + r) * TT + ord];
        }

        // ---- per-group wait: only my 2 producer CTAs (cols 64g..64g+64) ----
        if (t64 < 2)
            spin_until(&g_flag[((rb << 4) + 2 * g + t64) * 32], base + 1 + (unsigned)t);
        bar_named(1 + g, 64);

        // ---- fill my 64-k slice of the h tile (L1 bypass: lines are stale) ----
        #pragma unroll
        for (int j = 0; j < 8; ++j) {
            const int r = fr0 + 4 * j;
            float4 v = __ldcg((const float4*)(g_h[p] + (size_t)(row0g + r) * HH + KR * g) + fcc);
            *(float4*)(h_sm + r * LDH + KR * g + 4 * fcc) = v;
        }
        bar_named(1 + g, 64);

        // ---- 4x4 microtile over my 64-k range; f32x2-packed accumulators ----
        ull a00 = 0, a01 = 0, a02 = 0, a03 = 0;
        ull a10 = 0, a11 = 0, a12 = 0, a13 = 0;
        ull a20 = 0, a21 = 0, a22 = 0, a23 = 0;
        ull a30 = 0, a31 = 0, a32 = 0, a33 = 0;
        #pragma unroll 2
        for (int kk = 0; kk < KR; kk += 4) {
            ulonglong2 H0 = *(const ulonglong2*)(hb[0] + kk);
            ulonglong2 H1 = *(const ulonglong2*)(hb[1] + kk);
            ulonglong2 H2 = *(const ulonglong2*)(hb[2] + kk);
            ulonglong2 H3 = *(const ulonglong2*)(hb[3] + kk);
            ulonglong2 W0 = *(const ulonglong2*)(wb[0] + kk);
            ulonglong2 W1 = *(const ulonglong2*)(wb[1] + kk);
            ulonglong2 W2 = *(const ulonglong2*)(wb[2] + kk);
            ulonglong2 W3 = *(const ulonglong2*)(wb[3] + kk);
            a00 = ffma2(H0.x, W0.x, a00); a00 = ffma2(H0.y, W0.y, a00);
            a01 = ffma2(H0.x, W1.x, a01); a01 = ffma2(H0.y, W1.y, a01);
            a02 = ffma2(H0.x, W2.x, a02); a02 = ffma2(H0.y, W2.y, a02);
            a03 = ffma2(H0.x, W3.x, a03); a03 = ffma2(H0.y, W3.y, a03);
            a10 = ffma2(H1.x, W0.x, a10); a10 = ffma2(H1.y, W0.y, a10);
            a11 = ffma2(H1.x, W1.x, a11); a11 = ffma2(H1.y, W1.y, a11);
            a12 = ffma2(H1.x, W2.x, a12); a12 = ffma2(H1.y, W2.y, a12);
            a13 = ffma2(H1.x, W3.x, a13); a13 = ffma2(H1.y, W3.y, a13);
            a20 = ffma2(H2.x, W0.x, a20); a20 = ffma2(H2.y, W0.y, a20);
            a21 = ffma2(H2.x, W1.x, a21); a21 = ffma2(H2.y, W1.y, a21);
            a22 = ffma2(H2.x, W2.x, a22); a22 = ffma2(H2.y, W2.y, a22);
            a23 = ffma2(H2.x, W3.x, a23); a23 = ffma2(H2.y, W3.y, a23);
            a30 = ffma2(H3.x, W0.x, a30); a30 = ffma2(H3.y, W0.y, a30);
            a31 = ffma2(H3.x, W1.x, a31); a31 = ffma2(H3.y, W1.y, a31);
            a32 = ffma2(H3.x, W2.x, a32); a32 = ffma2(H3.y, W2.y, a32);
            a33 = ffma2(H3.x, W3.x, a33); a33 = ffma2(H3.y, W3.y, a33);
        }
        // publish partials: scratch[g][t64][0..15], stride SCR
        {
            float* dst = scratch + (size_t)(g * 64 + t64) * SCR;
            *(float4*)(dst +  0) = make_float4(u2sum(a00), u2sum(a01), u2sum(a02), u2sum(a03));
            *(float4*)(dst +  4) = make_float4(u2sum(a10), u2sum(a11), u2sum(a12), u2sum(a13));
            *(float4*)(dst +  8) = make_float4(u2sum(a20), u2sum(a21), u2sum(a22), u2sum(a23));
            *(float4*)(dst + 12) = make_float4(u2sum(a30), u2sum(a31), u2sum(a32), u2sum(a33));
        }
        __syncthreads();   // all partials visible

        // ---- distributed reduce: 2 outputs per thread (same row, cols col0l/col1l) ----
        {
            float2 acc = make_float2(0.f, 0.f);
            #pragma unroll
            for (int gg = 0; gg < NG; ++gg) {
                float2 v = *(const float2*)(scratch + (size_t)(gg * 64 + t64o) * SCR + idx);
                acc.x += v.x; acc.y += v.y;
            }
            const float xr = s_x[row_l];
            float v0 = tanhf(fmaf(xr, s_wb[col0l], s_wb[32 + col0l]) + acc.x);
            float v1 = tanhf(fmaf(xr, s_wb[col1l], s_wb[32 + col1l]) + acc.y);
            float* dst = g_h[p ^ 1] + (size_t)(row0g + row_l) * HH + col0g;
            dst[col0l] = v0;
            dst[col1l] = v1;
        }
        __syncthreads();   // all h_new stores done before release
        if (tid == 0) st_release(&g_flag[blockIdx.x * 32], base + 2 + (unsigned)t);
        p ^= 1;
    }
    // final h in g_h[0] (784 steps, even)

    // ---- Epilogue on block 0: wait whole grid, then head + log-softmax ----
    if (blockIdx.x == 0) {
        if (tid < NBLK)
            spin_until(&g_flag[tid * 32], base + 1 + TT);
        __syncthreads();

        __shared__ float s_loss[BB];
        __shared__ int   s_corr[BB];
        if (tid < BB) {
            const int b = tid;
            const float* hrow = g_h[0] + (size_t)b * HH;

            float logit[NC];
            #pragma unroll
            for (int c = 0; c < NC; ++c) logit[c] = lin_b[c];
            for (int k = 0; k < HH; k += 4) {
                float4 hv = __ldcg((const float4*)(hrow + k));
                #pragma unroll
                for (int c = 0; c < NC; ++c) {
                    float4 wv = *(const float4*)(lin_W + (size_t)c * HH + k);
                    logit[c] = fmaf(hv.x, wv.x, logit[c]);
                    logit[c] = fmaf(hv.y, wv.y, logit[c]);
                    logit[c] = fmaf(hv.z, wv.z, logit[c]);
                    logit[c] = fmaf(hv.w, wv.w, logit[c]);
                }
            }
            float m = logit[0]; int pred = 0;
            #pragma unroll
            for (int c = 1; c < NC; ++c)
                if (logit[c] > m) { m = logit[c]; pred = c; }
            float se = 0.f;
            #pragma unroll
            for (int c = 0; c < NC; ++c) se += expf(logit[c] - m);
            const float lse = m + logf(se);

            const int yb = is_i64 ? (int)((const long long*)y_raw)[b]
                                  : ((const int*)y_raw)[b];
            s_loss[b] = lse - logit[yb];
            s_corr[b] = (pred == yb) ? 1 : 0;
        }
        __syncthreads();
        if (tid == 0) {
            float L = 0.f; int C = 0;
            for (int i = 0; i < BB; ++i) { L += s_loss[i]; C += s_corr[i]; }
            out[0] = L / (float)BB;
            if (out_size >= 2) out[1] = (float)C;
        }
    }
}

extern "C" void kernel_launch(void* const* d_in, const int* in_sizes, int n_in,
                              void* d_out, int out_size) {
    // Identify inputs by element count (robust to ordering).
    const float *inputs = 0, *W_ih = 0, *b_ih = 0, *W_hh = 0, *b_hh = 0,
                *lin_W = 0, *lin_b = 0;
    const void *y = 0, *order = 0;
    int n512 = 0;
    for (int i = 0; i < n_in; ++i) {
        const int s = in_sizes[i];
        const void* ptr = d_in[i];
        if      (s == 200704) inputs = (const float*)ptr;
        else if (s == 262144) W_hh   = (const float*)ptr;
        else if (s == 5120)   lin_W  = (const float*)ptr;
        else if (s == 10)     lin_b  = (const float*)ptr;
        else if (s == 784)    order  = ptr;
        else if (s == 256)    y      = ptr;
        else if (s == 512) {
            if      (n512 == 0) W_ih = (const float*)ptr;
            else if (n512 == 1) b_ih = (const float*)ptr;
            else                b_hh = (const float*)ptr;
            ++n512;
        }
    }
    float* out = (float*)d_out;

    // smem: w[32][516] + h[32][516] + scratch[8][64][20] + order[784] + x[32] + wb[64] + u
    const size_t smem_bytes =
        ((size_t)64 * LDH + (size_t)NG * 64 * SCR) * sizeof(float)
        + TT * sizeof(int) + (32 + 64) * sizeof(float) + 64;
    cudaFuncSetAttribute(rnn_persistent,
                         cudaFuncAttributeMaxDynamicSharedMemorySize, (int)smem_bytes);
    rnn_persistent<<<NBLK, NTHR, smem_bytes>>>(inputs, y, order, W_ih, b_ih,
                                               W_hh, b_hh, lin_W, lin_b, out,
                                               out_size);
}

// round 8
// speedup vs baseline: 1.7832x; 1.0265x over previous
#include <cuda_runtime.h>
#include <math.h>

// Problem constants
#define BB   256
#define TT   784
#define HH   512
#define NC   10

// 8 row-groups x 16 col-blocks = 128 CTAs, all co-resident (1 CTA/SM)
#define NBLK 128
#define NTHR 512
#define NG   8              // k-groups per CTA
#define KR   64             // k-range per group (NG*KR = HH)
#define LDH  516            // smem row stride in floats: mod 32 == 4 -> conflict-free patterns
#define SCR  20             // scratch stride (floats) per (group,thread)
#define SPIN_CAP 10000000u  // watchdog: real waits are <1e3 polls; cap turns hang into signal

typedef unsigned long long ull;

// Scratch (device globals; no allocation)
__device__ __align__(16) float g_h[2][BB * HH];
__device__ __align__(16) float g_xT[TT * BB];   // inputs[:, order] transposed: [t][b]
__device__ unsigned g_flag[NBLK * 32];   // one flag per CTA, 128B apart; monotonic across replays

__device__ __forceinline__ ull ffma2(ull a, ull b, ull c) {
    ull d;
    asm("fma.rn.f32x2 %0, %1, %2, %3;" : "=l"(d) : "l"(a), "l"(b), "l"(c));
    return d;
}
__device__ __forceinline__ float u2sum(ull v) {
    float lo, hi;
    asm("mov.b64 {%0, %1}, %2;" : "=f"(lo), "=f"(hi) : "l"(v));
    return lo + hi;
}
__device__ __forceinline__ void st_release(unsigned* p, unsigned v) {
    asm volatile("st.release.gpu.global.u32 [%0], %1;" :: "l"(p), "r"(v) : "memory");
}
__device__ __forceinline__ unsigned ld_acquire(const unsigned* p) {
    unsigned v;
    asm volatile("ld.acquire.gpu.global.u32 %0, [%1];" : "=r"(v) : "l"(p) : "memory");
    return v;
}
__device__ __forceinline__ void bar_named(int id, int cnt) {
    asm volatile("bar.sync %0, %1;" :: "r"(id), "r"(cnt) : "memory");
}
// Bounded acquire-spin: waits until *p - target >= 0 (wrap-safe) or watchdog cap.
__device__ __forceinline__ void spin_until(const unsigned* p, unsigned target) {
    unsigned v, n = 0;
    do { v = ld_acquire(p); } while ((int)(v - target) < 0 && ++n < SPIN_CAP);
}

extern "C" __global__ void __launch_bounds__(NTHR, 1)
rnn_persistent(const float* __restrict__ inputs,     // (B, T) f32
               const void* __restrict__ y_raw,       // (B,)   i32/i64 (detected)
               const void* __restrict__ order_raw,   // (T,)   i32/i64 (detected)
               const float* __restrict__ W_ih,       // (H,1)
               const float* __restrict__ b_ih,       // (H,)
               const float* __restrict__ W_hh,       // (H,H)
               const float* __restrict__ b_hh,       // (H,)
               const float* __restrict__ lin_W,      // (10,H)
               const float* __restrict__ lin_b,      // (10,)
               float* __restrict__ out, int out_size)
{
    extern __shared__ float smem[];
    float* w_sm    = smem;                         // [32][LDH]
    float* h_sm    = smem + 32 * LDH;              // [32][LDH]
    float* scratch = smem + 64 * LDH;              // [NG][64][SCR]
    float* s_wb    = scratch + NG * 64 * SCR;      // [0..31]=w_ih, [32..63]=bias per local col
    unsigned* s_u  = (unsigned*)(s_wb + 64);       // [0]=base

    const int tid = threadIdx.x;
    const int g   = tid >> 6;            // k-group 0..7, owns k in [KR*g, KR*g+KR)
    const int t64 = tid & 63;
    const int ty  = t64 >> 3;            // 0..7  -> rows {ty, ty+8, ty+16, ty+24}
    const int tx  = t64 & 7;             // 0..7  -> cols {tx, tx+8, tx+16, tx+24}

    const int rb    = blockIdx.x >> 4;   // row group 0..7
    const int cb    = blockIdx.x & 15;   // col block 0..15
    const int row0g = rb * 32;
    const int col0g = cb * 32;

    const bool is_i64 = (((const int*)order_raw)[1] == 0);   // arange detect

    if (tid == 0) s_u[0] = g_flag[blockIdx.x * 32];

    // ---- W_hh slice into smem, [c_local][k] stride LDH: ONCE ----
    {
        const int c  = tid >> 4;         // local col 0..31
        const int p0 = tid & 15;
        const float4* src = (const float4*)(W_hh + (size_t)(col0g + c) * HH);
        float* dst = w_sm + c * LDH;
        #pragma unroll
        for (int it = 0; it < 8; ++it) {
            int cc = p0 + (it << 4);
            *(float4*)(dst + 4 * cc) = src[cc];
        }
    }
    // Per-col params into smem
    if (tid < 32) {
        int c = col0g + tid;
        s_wb[tid]      = W_ih[c];
        s_wb[32 + tid] = b_ih[c] + b_hh[c];
    }
    // Zero h0 for our tile
    {
        int zr = tid >> 4, zc = (tid & 15) << 1;
        *(float2*)(g_h[0] + (size_t)(row0g + zr) * HH + col0g + zc) = make_float2(0.f, 0.f);
    }
    // ---- ONE-TIME x transpose: this CTA fills g_xT[t][row0g..+32] for its t-slice.
    // Consumers (same row group) are guarded by the base+1 flag they already wait on.
    {
        for (int idx = tid; idx < 49 * 32; idx += NTHR) {
            const int tt = 49 * cb + (idx >> 5);   // 784 = 16 * 49
            const int r  = idx & 31;
            const int o  = is_i64 ? (int)((const long long*)order_raw)[tt]
                                  : ((const int*)order_raw)[tt];
            g_xT[(size_t)tt * BB + row0g + r] = inputs[(size_t)(row0g + r) * TT + o];
        }
    }
    __syncthreads();
    const unsigned base = s_u[0];
    if (tid == 0) st_release(&g_flag[blockIdx.x * 32], base + 1);   // h0 + xT slice ready

    // Compute-phase pointers
    const float* hb[4];
    const float* wb[4];
    #pragma unroll
    for (int i = 0; i < 4; ++i) hb[i] = h_sm + (ty + 8 * i) * LDH + KR * g;
    #pragma unroll
    for (int j = 0; j < 4; ++j) wb[j] = w_sm + (tx + 8 * j) * LDH + KR * g;

    // Fill mapping: rows fr0+4j (j=0..7), float4 chunk fcc within my 64-float slice
    const int fr0 = t64 >> 4, fcc = t64 & 15;

    // Reduce mapping (coalesced stores): warp rw owns rows {2rw, 2rw+1};
    // lane: row_l = 2rw + (lane>>4), cols {2m, 2m+1} with m = lane&15.
    const int rw    = tid >> 5;
    const int lane  = tid & 31;
    const int row_l = 2 * rw + (lane >> 4);
    const int m     = lane & 15;
    const int c0    = 2 * m, c1 = 2 * m + 1;
    const int own0  = ((row_l & 7) << 3) | (c0 & 7);
    const int own1  = own0 + 1;                       // (c1&7) = (c0&7)+1
    const int slot  = ((row_l >> 3) << 2) | (c0 >> 3);

    int p = 0;
    for (int t = 0; t < TT; ++t) {
        // ---- per-group wait: only my 2 producer CTAs (cols 64g..64g+64) ----
        if (t64 < 2)
            spin_until(&g_flag[((rb << 4) + 2 * g + t64) * 32], base + 1 + (unsigned)t);
        bar_named(1 + g, 64);

        // ---- fill my 64-k slice of the h tile (L1 bypass: lines are stale) ----
        #pragma unroll
        for (int j = 0; j < 8; ++j) {
            const int r = fr0 + 4 * j;
            float4 v = __ldcg((const float4*)(g_h[p] + (size_t)(row0g + r) * HH + KR * g) + fcc);
            *(float4*)(h_sm + r * LDH + KR * g + 4 * fcc) = v;
        }
        bar_named(1 + g, 64);

        // ---- 4x4 microtile over my 64-k range; f32x2-packed accumulators ----
        ull a00 = 0, a01 = 0, a02 = 0, a03 = 0;
        ull a10 = 0, a11 = 0, a12 = 0, a13 = 0;
        ull a20 = 0, a21 = 0, a22 = 0, a23 = 0;
        ull a30 = 0, a31 = 0, a32 = 0, a33 = 0;
        #pragma unroll 2
        for (int kk = 0; kk < KR; kk += 4) {
            ulonglong2 H0 = *(const ulonglong2*)(hb[0] + kk);
            ulonglong2 H1 = *(const ulonglong2*)(hb[1] + kk);
            ulonglong2 H2 = *(const ulonglong2*)(hb[2] + kk);
            ulonglong2 H3 = *(const ulonglong2*)(hb[3] + kk);
            ulonglong2 W0 = *(const ulonglong2*)(wb[0] + kk);
            ulonglong2 W1 = *(const ulonglong2*)(wb[1] + kk);
            ulonglong2 W2 = *(const ulonglong2*)(wb[2] + kk);
            ulonglong2 W3 = *(const ulonglong2*)(wb[3] + kk);
            a00 = ffma2(H0.x, W0.x, a00); a00 = ffma2(H0.y, W0.y, a00);
            a01 = ffma2(H0.x, W1.x, a01); a01 = ffma2(H0.y, W1.y, a01);
            a02 = ffma2(H0.x, W2.x, a02); a02 = ffma2(H0.y, W2.y, a02);
            a03 = ffma2(H0.x, W3.x, a03); a03 = ffma2(H0.y, W3.y, a03);
            a10 = ffma2(H1.x, W0.x, a10); a10 = ffma2(H1.y, W0.y, a10);
            a11 = ffma2(H1.x, W1.x, a11); a11 = ffma2(H1.y, W1.y, a11);
            a12 = ffma2(H1.x, W2.x, a12); a12 = ffma2(H1.y, W2.y, a12);
            a13 = ffma2(H1.x, W3.x, a13); a13 = ffma2(H1.y, W3.y, a13);
            a20 = ffma2(H2.x, W0.x, a20); a20 = ffma2(H2.y, W0.y, a20);
            a21 = ffma2(H2.x, W1.x, a21); a21 = ffma2(H2.y, W1.y, a21);
            a22 = ffma2(H2.x, W2.x, a22); a22 = ffma2(H2.y, W2.y, a22);
            a23 = ffma2(H2.x, W3.x, a23); a23 = ffma2(H2.y, W3.y, a23);
            a30 = ffma2(H3.x, W0.x, a30); a30 = ffma2(H3.y, W0.y, a30);
            a31 = ffma2(H3.x, W1.x, a31); a31 = ffma2(H3.y, W1.y, a31);
            a32 = ffma2(H3.x, W2.x, a32); a32 = ffma2(H3.y, W2.y, a32);
            a33 = ffma2(H3.x, W3.x, a33); a33 = ffma2(H3.y, W3.y, a33);
        }
        // publish partials: scratch[g][t64][0..15], stride SCR (conflict-free STS.128)
        {
            float* dst = scratch + (size_t)(g * 64 + t64) * SCR;
            *(float4*)(dst +  0) = make_float4(u2sum(a00), u2sum(a01), u2sum(a02), u2sum(a03));
            *(float4*)(dst +  4) = make_float4(u2sum(a10), u2sum(a11), u2sum(a12), u2sum(a13));
            *(float4*)(dst +  8) = make_float4(u2sum(a20), u2sum(a21), u2sum(a22), u2sum(a23));
            *(float4*)(dst + 12) = make_float4(u2sum(a30), u2sum(a31), u2sum(a32), u2sum(a33));
        }
        __syncthreads();   // all partials visible

        // ---- distributed reduce: contiguous float2 per thread -> coalesced STG.64 ----
        {
            float acc0 = 0.f, acc1 = 0.f;
            #pragma unroll
            for (int gg = 0; gg < NG; ++gg) {
                const float* sc = scratch + (size_t)(gg * 64) * SCR;
                acc0 += sc[(size_t)own0 * SCR + slot];
                acc1 += sc[(size_t)own1 * SCR + slot];
            }
            const float xr = g_xT[(size_t)t * BB + row0g + row_l];   // L2-resident, coalesced
            float v0 = tanhf(fmaf(xr, s_wb[c0], s_wb[32 + c0]) + acc0);
            float v1 = tanhf(fmaf(xr, s_wb[c1], s_wb[32 + c1]) + acc1);
            *(float2*)(g_h[p ^ 1] + (size_t)(row0g + row_l) * HH + col0g + c0) =
                make_float2(v0, v1);
        }
        __syncthreads();   // all h_new stores done before release
        if (tid == 0) st_release(&g_flag[blockIdx.x * 32], base + 2 + (unsigned)t);
        p ^= 1;
    }
    // final h in g_h[0] (784 steps, even)

    // ---- Epilogue on block 0: wait whole grid, then head + log-softmax ----
    if (blockIdx.x == 0) {
        if (tid < NBLK)
            spin_until(&g_flag[tid * 32], base + 1 + TT);
        __syncthreads();

        __shared__ float s_loss[BB];
        __shared__ int   s_corr[BB];
        if (tid < BB) {
            const int b = tid;
            const float* hrow = g_h[0] + (size_t)b * HH;

            float logit[NC];
            #pragma unroll
            for (int c = 0; c < NC; ++c) logit[c] = lin_b[c];
            for (int k = 0; k < HH; k += 4) {
                float4 hv = __ldcg((const float4*)(hrow + k));
                #pragma unroll
                for (int c = 0; c < NC; ++c) {
                    float4 wv = *(const float4*)(lin_W + (size_t)c * HH + k);
                    logit[c] = fmaf(hv.x, wv.x, logit[c]);
                    logit[c] = fmaf(hv.y, wv.y, logit[c]);
                    logit[c] = fmaf(hv.z, wv.z, logit[c]);
                    logit[c] = fmaf(hv.w, wv.w, logit[c]);
                }
            }
            float mx = logit[0]; int pred = 0;
            #pragma unroll
            for (int c = 1; c < NC; ++c)
                if (logit[c] > mx) { mx = logit[c]; pred = c; }
            float se = 0.f;
            #pragma unroll
            for (int c = 0; c < NC; ++c) se += expf(logit[c] - mx);
            const float lse = mx + logf(se);

            const int yb = is_i64 ? (int)((const long long*)y_raw)[b]
                                  : ((const int*)y_raw)[b];
            s_loss[b] = lse - logit[yb];
            s_corr[b] = (pred == yb) ? 1 : 0;
        }
        __syncthreads();
        if (tid == 0) {
            float L = 0.f; int C = 0;
            for (int i = 0; i < BB; ++i) { L += s_loss[i]; C += s_corr[i]; }
            out[0] = L / (float)BB;
            if (out_size >= 2) out[1] = (float)C;
        }
    }
}

extern "C" void kernel_launch(void* const* d_in, const int* in_sizes, int n_in,
                              void* d_out, int out_size) {
    // Identify inputs by element count (robust to ordering).
    const float *inputs = 0, *W_ih = 0, *b_ih = 0, *W_hh = 0, *b_hh = 0,
                *lin_W = 0, *lin_b = 0;
    const void *y = 0, *order = 0;
    int n512 = 0;
    for (int i = 0; i < n_in; ++i) {
        const int s = in_sizes[i];
        const void* ptr = d_in[i];
        if      (s == 200704) inputs = (const float*)ptr;
        else if (s == 262144) W_hh   = (const float*)ptr;
        else if (s == 5120)   lin_W  = (const float*)ptr;
        else if (s == 10)     lin_b  = (const float*)ptr;
        else if (s == 784)    order  = ptr;
        else if (s == 256)    y      = ptr;
        else if (s == 512) {
            if      (n512 == 0) W_ih = (const float*)ptr;
            else if (n512 == 1) b_ih = (const float*)ptr;
            else                b_hh = (const float*)ptr;
            ++n512;
        }
    }
    float* out = (float*)d_out;

    // smem: w[32][516] + h[32][516] + scratch[8][64][20] + wb[64] + u
    const size_t smem_bytes =
        ((size_t)64 * LDH + (size_t)NG * 64 * SCR + 64) * sizeof(float) + 64;
    cudaFuncSetAttribute(rnn_persistent,
                         cudaFuncAttributeMaxDynamicSharedMemorySize, (int)smem_bytes);
    rnn_persistent<<<NBLK, NTHR, smem_bytes>>>(inputs, y, order, W_ih, b_ih,
                                               W_hh, b_hh, lin_W, lin_b, out,
                                               out_size);
}